// round 12
// baseline (speedup 1.0000x reference)
#include <cuda_runtime.h>
#include <cuda_fp16.h>
#include <cstdint>

#define BB 64
#define HH 256
#define WW 256
#define TH 64                      // output rows per tile
#define NT 256
#define ARX (TH + 10)              // 74 bits-rows incl R=5 halo
#define SBW 10                     // padded bits row: zero word each side of 8

typedef unsigned long long ull;

__device__ __align__(16) uint32_t g_bits[3][BB][HH][8];   // 1 bit/px masks
__device__ float g_max[3 * BB];    // zero-init; atomicMax idempotent across replays

__device__ __forceinline__ int map_ch(int m) { return (m == 0) ? 2 : (m == 1) ? 1 : 3; }

// ---- packed f32x2 helpers (sm_103a) ----
__device__ __forceinline__ ull f2pack(uint32_t lo, uint32_t hi) {
    ull r; asm("mov.b64 %0, {%1, %2};" : "=l"(r) : "r"(lo), "r"(hi)); return r;
}
__device__ __forceinline__ void f2unpack(ull v, float& lo, float& hi) {
    asm("mov.b64 {%0, %1}, %2;" : "=f"(lo), "=f"(hi) : "l"(v));
}
__device__ __forceinline__ ull f2add(ull a, ull b) {
    ull r; asm("add.rn.f32x2 %0, %1, %2;" : "=l"(r) : "l"(a), "l"(b)); return r;
}
__device__ __forceinline__ ull f2mul(ull a, ull b) {
    ull r; asm("mul.rn.f32x2 %0, %1, %2;" : "=l"(r) : "l"(a), "l"(b)); return r;
}
__device__ __forceinline__ ull f2fma(ull a, ull b, ull c) {
    ull r; asm("fma.rn.f32x2 %0, %1, %2, %3;" : "=l"(r) : "l"(a), "l"(b), "l"(c)); return r;
}

// ============ Kernel 1: threshold channels into bit array + ch0 copy ============
__global__ void __launch_bounds__(NT) bitK(const float* __restrict__ x,
                                           float* __restrict__ out) {
    const int b = blockIdx.y;
    const int z = blockIdx.z;
    const size_t plane = (size_t)HH * WW;

    if (z == 3) {                       // ch0 passthrough
        const size_t off = (size_t)blockIdx.x * 8192;
        const float4* s = (const float4*)(x + (size_t)b * 4 * plane + off);
        float4* d = (float4*)(out + (size_t)b * 5 * plane + off);
#pragma unroll
        for (int k = 0; k < 8; k++)
            d[threadIdx.x + 256 * k] = s[threadIdx.x + 256 * k];
        return;
    }

    const int m = z;
    const float* src = x + ((size_t)b * 4 + map_ch(m)) * plane;
    const int warp = threadIdx.x >> 5;
    const int lane = threadIdx.x & 31;
    const int r0 = blockIdx.x * 32 + warp * 4;

#pragma unroll
    for (int rr = 0; rr < 4; rr++) {
        const int r = r0 + rr;
        const float* rp = src + (size_t)r * WW;
        float v[8];
#pragma unroll
        for (int k = 0; k < 8; k++) v[k] = rp[32 * k + lane];
        uint32_t mine = 0;
#pragma unroll
        for (int k = 0; k < 8; k++) {
            uint32_t w = __ballot_sync(0xFFFFFFFFu, v[k] > 0.f);
            if (lane == k) mine = w;
        }
        if (lane < 8) g_bits[m][b][r][lane] = mine;
    }
}

// ============ paired 12-bit LUT: entry e -> f32x2{ s(e bits0..2R), s(e bits1..2R+1) } ============
template <int R>
__device__ __forceinline__ void buildLUT12(const float* wg, ull* LUT) {
    constexpr int NB = 2 * R + 1;
    constexpr int NE = 1 << (NB + 1);
    for (int e = threadIdx.x; e < NE; e += NT) {
        float s0 = 0.f, s1 = 0.f;
#pragma unroll
        for (int p = 0; p < NB; p++) {
            float w = wg[p < R ? R - p : p - R];
            if ((e >> p) & 1) s0 += w;
            if ((e >> (p + 1)) & 1) s1 += w;
        }
        LUT[e] = f2pack(__float_as_uint(s0), __float_as_uint(s1));
    }
}

template <int R>
__device__ __forceinline__ void fillSb(int m, int b, int row0, uint32_t (*Sb)[SBW]) {
    constexpr int AR = TH + 2 * R;
    for (int idx = threadIdx.x; idx < AR * 8; idx += NT) {
        const int r = idx >> 3, w = idx & 7;
        const int gr = row0 - R + r;
        Sb[r][w + 1] = ((unsigned)gr < HH) ? g_bits[m][b][gr][w] : 0u;
    }
    for (int idx = threadIdx.x; idx < AR * 2; idx += NT)
        Sb[idx >> 1][(idx & 1) ? 9 : 0] = 0u;
}

// ============ single-pass conv over a 32-row x 2-col strip ============
// MODE: 0 = max-only | 1 = write normalized channel | 2 = save raw fp16 pairs | 3 = write c + mul
template <int R, int MODE>
__device__ __forceinline__ float convPass(const uint32_t (*Sb)[SBW], const ull* LUT,
                                          const ull* w2, int row0, int jc, int t0,
                                          float so, float st, uint32_t* th2,
                                          float* och, float* omul) {
    constexpr int W = 2 * R + 1;
    const int bitpos = jc + 32 - R;
    const int wi = bitpos >> 5;
    const unsigned sh = bitpos & 31u;
    const uint32_t msk = (1u << (W + 1)) - 1u;

    ull win[W];
#pragma unroll
    for (int k = 0; k < W; k++) {
        uint32_t v = __funnelshift_r(Sb[t0 + k][wi], Sb[t0 + k][wi + 1], sh) & msk;
        win[k] = LUT[v];
    }
    float mx = 0.f;
#pragma unroll
    for (int t = 0; t < 32; t++) {
        ull acc = f2mul(w2[0], win[R]);
#pragma unroll
        for (int d = 1; d <= R; d++)
            acc = f2fma(w2[d], f2add(win[R - d], win[R + d]), acc);
        float lo, hi; f2unpack(acc, lo, hi);
        if (MODE == 0) {
            mx = fmaxf(mx, fmaxf(lo, hi));
        } else if (MODE == 1) {
            *(float2*)(och + (size_t)(row0 + t0 + t) * WW + jc) =
                make_float2(lo * so, hi * so);
        } else if (MODE == 2) {
            uint32_t h2;   // low half = lo (col jc)
            asm("cvt.rn.f16x2.f32 %0, %1, %2;" : "=r"(h2) : "f"(hi), "f"(lo));
            th2[t] = h2;
        } else {
            float cl = lo * so, ch = hi * so;
            *(float2*)(och + (size_t)(row0 + t0 + t) * WW + jc) = make_float2(cl, ch);
            float2 tr = __half22float2(*(__half2*)&th2[t]);
            *(float2*)(omul + (size_t)(row0 + t0 + t) * WW + jc) =
                make_float2(tr.x * st * cl, tr.y * st * ch);
        }
#pragma unroll
        for (int k = 0; k < W - 1; k++) win[k] = win[k + 1];
        if (t < 31) {
            uint32_t v = __funnelshift_r(Sb[t0 + t + W][wi], Sb[t0 + t + W][wi + 1], sh) & msk;
            win[W - 1] = LUT[v];
        }
    }
    return mx;
}

__device__ __forceinline__ float invMax(float m) { return 1.0f / ((m == 0.f) ? 1.f : m); }

// ============ Kernel 2: per-(m,b) maxes (conv, no map stores) ============
__global__ void __launch_bounds__(NT) maxK() {
    __shared__ ull LUT[4096];
    __shared__ uint32_t Sb[ARX][SBW];
    __shared__ float red[8];

    const int row0 = blockIdx.x * TH;
    const int b = blockIdx.y;
    const int m = blockIdx.z;
    const int jc = (threadIdx.x & 127) * 2;
    const int t0 = (threadIdx.x >> 7) * 32;

    float mx;
    if (m == 2) {
        float wg[3];
#pragma unroll
        for (int d = 0; d <= 2; d++) wg[d] = __expf(-(float)(d * d) * 2.0f);
        buildLUT12<2>(wg, LUT);
        fillSb<2>(2, b, row0, Sb);
        __syncthreads();
        ull w2[3];
#pragma unroll
        for (int d = 0; d <= 2; d++) w2[d] = f2pack(__float_as_uint(wg[d]), __float_as_uint(wg[d]));
        mx = convPass<2, 0>(Sb, LUT, w2, row0, jc, t0, 0.f, 0.f, nullptr, nullptr, nullptr);
    } else {
        float wg[6];
#pragma unroll
        for (int d = 0; d <= 5; d++) wg[d] = __expf(-(float)(d * d) * 0.5f);
        buildLUT12<5>(wg, LUT);
        fillSb<5>(m, b, row0, Sb);
        __syncthreads();
        ull w2[6];
#pragma unroll
        for (int d = 0; d <= 5; d++) w2[d] = f2pack(__float_as_uint(wg[d]), __float_as_uint(wg[d]));
        mx = convPass<5, 0>(Sb, LUT, w2, row0, jc, t0, 0.f, 0.f, nullptr, nullptr, nullptr);
    }

#pragma unroll
    for (int o = 16; o; o >>= 1)
        mx = fmaxf(mx, __shfl_xor_sync(0xFFFFFFFFu, mx, o));
    if ((threadIdx.x & 31) == 0) red[threadIdx.x >> 5] = mx;
    __syncthreads();
    if (threadIdx.x < 8) {
        float v = red[threadIdx.x];
#pragma unroll
        for (int o = 4; o; o >>= 1)
            v = fmaxf(v, __shfl_xor_sync(0xFFu, v, o));
        if (threadIdx.x == 0)
            atomicMax((int*)&g_max[m * BB + b], __float_as_int(v));
    }
}

// ============ Kernel 3: recompute conv, normalize, write ch1..ch4 ============
__global__ void __launch_bounds__(NT) finK(float* __restrict__ out) {
    __shared__ ull LUT[4096];
    __shared__ uint32_t Sb[2][ARX][SBW];

    const int row0 = blockIdx.x * TH;
    const int b = blockIdx.y;
    const int m = blockIdx.z;
    const int jc = (threadIdx.x & 127) * 2;
    const int t0 = (threadIdx.x >> 7) * 32;
    const size_t plane = (size_t)HH * WW;
    float* ob = out + (size_t)b * 5 * plane;

    if (m == 2) {                        // hist -> ch3
        float wg[3];
#pragma unroll
        for (int d = 0; d <= 2; d++) wg[d] = __expf(-(float)(d * d) * 2.0f);
        buildLUT12<2>(wg, LUT);
        fillSb<2>(2, b, row0, Sb[0]);
        __syncthreads();
        ull w2[3];
#pragma unroll
        for (int d = 0; d <= 2; d++) w2[d] = f2pack(__float_as_uint(wg[d]), __float_as_uint(wg[d]));
        const float sh = invMax(g_max[2 * BB + b]);
        convPass<2, 1>(Sb[0], LUT, w2, row0, jc, t0, sh, 0.f, nullptr, ob + 3 * plane, nullptr);
    } else {
        float wg[6];
#pragma unroll
        for (int d = 0; d <= 5; d++) wg[d] = __expf(-(float)(d * d) * 0.5f);
        buildLUT12<5>(wg, LUT);
        ull w2[6];
#pragma unroll
        for (int d = 0; d <= 5; d++) w2[d] = f2pack(__float_as_uint(wg[d]), __float_as_uint(wg[d]));

        if (m == 0) {                    // target -> ch1
            fillSb<5>(0, b, row0, Sb[0]);
            __syncthreads();
            const float st = invMax(g_max[b]);
            convPass<5, 1>(Sb[0], LUT, w2, row0, jc, t0, st, 0.f, nullptr, ob + plane, nullptr);
        } else {                         // cost -> ch2, and target*cost -> ch4
            fillSb<5>(0, b, row0, Sb[0]);    // target bits
            fillSb<5>(1, b, row0, Sb[1]);    // cost bits
            __syncthreads();
            const float st = invMax(g_max[b]);
            const float sc = invMax(g_max[BB + b]);
            uint32_t th2[32];
            convPass<5, 2>(Sb[0], LUT, w2, row0, jc, t0, 0.f, 0.f, th2, nullptr, nullptr);
            convPass<5, 3>(Sb[1], LUT, w2, row0, jc, t0, sc, st, th2,
                           ob + 2 * plane, ob + 4 * plane);
        }
    }
}

extern "C" void kernel_launch(void* const* d_in, const int* in_sizes, int n_in,
                              void* d_out, int out_size) {
    const float* x = (const float*)d_in[0];
    float* out = (float*)d_out;

    bitK<<<dim3(8, BB, 4), NT>>>(x, out);
    maxK<<<dim3(HH / TH, BB, 3), NT>>>();
    finK<<<dim3(HH / TH, BB, 3), NT>>>(out);
}

// round 13
// speedup vs baseline: 1.0748x; 1.0748x over previous
#include <cuda_runtime.h>
#include <cuda_fp16.h>
#include <cstdint>

#define BB 64
#define HH 256
#define WW 256
#define TH 64                      // output rows per map tile
#define NT 256
#define ARX (TH + 10)              // 74 rows incl R=5 halo
#define SBW 10                     // padded bits row: zero word each side of 8

typedef unsigned long long ull;

__device__ __align__(16) uint32_t g_maph[3][BB][HH * WW / 2];  // fp16x2 unnormalized maps
__device__ float g_max[3 * BB];    // zero-init; atomicMax idempotent across replays

__device__ __forceinline__ int map_ch(int m) { return (m == 0) ? 2 : (m == 1) ? 1 : 3; }

// ---- packed f32x2 helpers (sm_103a) ----
__device__ __forceinline__ ull f2pack(uint32_t lo, uint32_t hi) {
    ull r; asm("mov.b64 %0, {%1, %2};" : "=l"(r) : "r"(lo), "r"(hi)); return r;
}
__device__ __forceinline__ void f2unpack(ull v, float& lo, float& hi) {
    asm("mov.b64 {%0, %1}, %2;" : "=f"(lo), "=f"(hi) : "l"(v));
}
__device__ __forceinline__ ull f2add(ull a, ull b) {
    ull r; asm("add.rn.f32x2 %0, %1, %2;" : "=l"(r) : "l"(a), "l"(b)); return r;
}
__device__ __forceinline__ ull f2mul(ull a, ull b) {
    ull r; asm("mul.rn.f32x2 %0, %1, %2;" : "=l"(r) : "l"(a), "l"(b)); return r;
}
__device__ __forceinline__ ull f2fma(ull a, ull b, ull c) {
    ull r; asm("fma.rn.f32x2 %0, %1, %2, %3;" : "=l"(r) : "l"(a), "l"(b), "l"(c)); return r;
}

// ============ LUT build: LUT[i] = sum over set bits p of wg[|p - R|] ============
template <int R>
__device__ __forceinline__ void buildLUT(const float* wg, float* LUT) {
    if constexpr (R == 5) {
        const int t = threadIdx.x;           // entry i = t*8 + j; bits 3..10 from t
        float base = 0.f;
#pragma unroll
        for (int b = 0; b < 8; b++) {
            int pos = b + 3;
            int ai = (pos < 5) ? (5 - pos) : (pos - 5);
            if ((t >> b) & 1) base += wg[ai];
        }
        float comb[8];
        comb[0] = 0.f;           comb[1] = wg[5];
        comb[2] = wg[4];         comb[3] = wg[5] + wg[4];
        comb[4] = wg[3];         comb[5] = wg[3] + wg[5];
        comb[6] = wg[3] + wg[4]; comb[7] = wg[3] + wg[4] + wg[5];
#pragma unroll
        for (int j = 0; j < 8; j++) LUT[t * 8 + j] = base + comb[j];
    } else {
        if (threadIdx.x < 32) {
            const int i = threadIdx.x;
            float s = 0.f;
#pragma unroll
            for (int b = 0; b < 5; b++) {
                int ai = (b < 2) ? (2 - b) : (b - 2);
                if ((i >> b) & 1) s += wg[ai];
            }
            LUT[i] = s;
        }
    }
}

// ============ Kernel A: inline threshold + single-pass conv (+ ch0 copy slice) ============
// z<3: one block = (64-row tile, b, map m). Fill bits tile by warp ballots from x,
//      then rolling-window conv -> fp16x2 map + per-(m,b) atomicMax.
// z=3: ch0 passthrough.
template <int R, int M>
__device__ __forceinline__ void runMap(const float* __restrict__ x, int b, float i2s,
                                       int row0, float* LUT, uint32_t (*Sb)[SBW],
                                       float* red) {
    constexpr int W = 2 * R + 1;
    constexpr int AR = TH + 2 * R;

    float wg[R + 1];
#pragma unroll
    for (int d = 0; d <= R; d++) wg[d] = __expf(-(float)(d * d) * i2s);

    buildLUT<R>(wg, LUT);

    // Inline fill: warp ballots 8 words per row straight into Sb (no global bits).
    const float* src = x + ((size_t)b * 4 + map_ch(M)) * (size_t)(HH * WW);
    const int warp = threadIdx.x >> 5;
    const int lane = threadIdx.x & 31;
    for (int r = warp; r < AR; r += NT / 32) {
        const int gr = row0 - R + r;
        const bool valid = ((unsigned)gr < HH);
        const float* rp = src + (size_t)(valid ? gr : 0) * WW;
        float v[8];
#pragma unroll
        for (int k = 0; k < 8; k++) v[k] = valid ? rp[32 * k + lane] : 0.f;
        uint32_t mine = 0;
#pragma unroll
        for (int k = 0; k < 8; k++) {
            uint32_t w = __ballot_sync(0xFFFFFFFFu, v[k] > 0.f);
            if (lane == k) mine = w;
        }
        if (lane < 8) Sb[r][lane + 1] = mine;
        else if (lane == 8) Sb[r][0] = 0u;
        else if (lane == 9) Sb[r][9] = 0u;
    }
    __syncthreads();

    ull w2[R + 1];
#pragma unroll
    for (int d = 0; d <= R; d++)
        w2[d] = f2pack(__float_as_uint(wg[d]), __float_as_uint(wg[d]));

    const int jc = (threadIdx.x & 127) * 2;   // column pair
    const int t0 = (threadIdx.x >> 7) * 32;   // row group

    const int bitpos = jc + 32 - R;
    const int wi = bitpos >> 5;
    const unsigned sh = bitpos & 31u;
    const uint32_t msk = (1u << W) - 1u;

    ull win[W];
#pragma unroll
    for (int k = 0; k < W; k++) {
        uint32_t v = __funnelshift_r(Sb[t0 + k][wi], Sb[t0 + k][wi + 1], sh);
        win[k] = f2pack(__float_as_uint(LUT[v & msk]),
                        __float_as_uint(LUT[(v >> 1) & msk]));
    }

    uint32_t* gdst = g_maph[M][b];
    float mx = 0.f;
#pragma unroll
    for (int t = 0; t < 32; t++) {
        ull acc = f2mul(w2[0], win[R]);
#pragma unroll
        for (int d = 1; d <= R; d++)
            acc = f2fma(w2[d], f2add(win[R - d], win[R + d]), acc);
        float lo, hi; f2unpack(acc, lo, hi);
        uint32_t h2;
        asm("cvt.rn.f16x2.f32 %0, %1, %2;" : "=r"(h2) : "f"(hi), "f"(lo));
        gdst[(size_t)(row0 + t0 + t) * (WW / 2) + (jc >> 1)] = h2;
        mx = fmaxf(mx, fmaxf(lo, hi));
#pragma unroll
        for (int k = 0; k < W - 1; k++) win[k] = win[k + 1];
        if (t < 31) {
            uint32_t v = __funnelshift_r(Sb[t0 + t + W][wi], Sb[t0 + t + W][wi + 1], sh);
            win[W - 1] = f2pack(__float_as_uint(LUT[v & msk]),
                                __float_as_uint(LUT[(v >> 1) & msk]));
        }
    }

    // block max -> one atomic (values >= 0; int compare order-preserving)
#pragma unroll
    for (int o = 16; o; o >>= 1)
        mx = fmaxf(mx, __shfl_xor_sync(0xFFFFFFFFu, mx, o));
    if ((threadIdx.x & 31) == 0) red[threadIdx.x >> 5] = mx;
    __syncthreads();
    if (threadIdx.x < 8) {
        float v = red[threadIdx.x];
#pragma unroll
        for (int o = 4; o; o >>= 1)
            v = fmaxf(v, __shfl_xor_sync(0xFFu, v, o));
        if (threadIdx.x == 0)
            atomicMax((int*)&g_max[M * BB + b], __float_as_int(v));
    }
}

__global__ void __launch_bounds__(NT) mapK(const float* __restrict__ x,
                                           float* __restrict__ out) {
    __shared__ float LUT[2048];
    __shared__ uint32_t Sb[ARX][SBW];
    __shared__ float red[8];

    const int row0 = blockIdx.x * TH;
    const int b = blockIdx.y;
    const int m = blockIdx.z;
    const size_t plane = (size_t)HH * WW;

    if (m == 3) {                       // ch0 passthrough: 16384 floats per block
        const size_t off = (size_t)blockIdx.x * 16384;
        const float4* s = (const float4*)(x + (size_t)b * 4 * plane + off);
        float4* d = (float4*)(out + (size_t)b * 5 * plane + off);
#pragma unroll
        for (int k = 0; k < 16; k++)
            d[threadIdx.x + 256 * k] = s[threadIdx.x + 256 * k];
        return;
    }

    if (m == 2)
        runMap<2, 2>(x, b, 2.0f, row0, LUT, Sb, red);   // hist,   sigma=0.5
    else if (m == 1)
        runMap<5, 1>(x, b, 0.5f, row0, LUT, Sb, red);   // cost,   sigma=1
    else
        runMap<5, 0>(x, b, 0.5f, row0, LUT, Sb, red);   // target, sigma=1
}

// ============ Kernel B: normalize + write ch1..ch4 (R11-identical) ============
__global__ void __launch_bounds__(256) finK(float* __restrict__ out) {
    const int b = blockIdx.y;
    const size_t px = ((size_t)blockIdx.x << 10) | ((size_t)threadIdx.x << 2);
    const size_t plane = (size_t)HH * WW;

    float mt = g_max[b];          float st = 1.0f / ((mt == 0.f) ? 1.f : mt);
    float mc = g_max[BB + b];     float sc = 1.0f / ((mc == 0.f) ? 1.f : mc);
    float mh = g_max[2 * BB + b]; float sh = 1.0f / ((mh == 0.f) ? 1.f : mh);

    uint2 tw = *(const uint2*)(&g_maph[0][b][px >> 1]);
    uint2 cw = *(const uint2*)(&g_maph[1][b][px >> 1]);
    uint2 hw = *(const uint2*)(&g_maph[2][b][px >> 1]);

    float2 ta = __half22float2(*(__half2*)&tw.x), tb = __half22float2(*(__half2*)&tw.y);
    float2 ca = __half22float2(*(__half2*)&cw.x), cb = __half22float2(*(__half2*)&cw.y);
    float2 ha = __half22float2(*(__half2*)&hw.x), hb = __half22float2(*(__half2*)&hw.y);

    float4 t = make_float4(ta.x * st, ta.y * st, tb.x * st, tb.y * st);
    float4 c = make_float4(ca.x * sc, ca.y * sc, cb.x * sc, cb.y * sc);
    float4 h = make_float4(ha.x * sh, ha.y * sh, hb.x * sh, hb.y * sh);
    float4 mu = make_float4(t.x * c.x, t.y * c.y, t.z * c.z, t.w * c.w);

    float* ob = out + (size_t)b * 5 * plane;
    *(float4*)(ob + plane + px) = t;
    *(float4*)(ob + 2 * plane + px) = c;
    *(float4*)(ob + 3 * plane + px) = h;
    *(float4*)(ob + 4 * plane + px) = mu;
}

extern "C" void kernel_launch(void* const* d_in, const int* in_sizes, int n_in,
                              void* d_out, int out_size) {
    const float* x = (const float*)d_in[0];
    float* out = (float*)d_out;

    mapK<<<dim3(HH / TH, BB, 4), NT>>>(x, out);
    finK<<<dim3(64, BB), 256>>>(out);
}